// round 6
// baseline (speedup 1.0000x reference)
#include <cuda_runtime.h>
#include <cstdint>

// WaveNet dilated causal conv stack.
// 2-CTA cluster per batch element, fused conv+io, ping-pong h in SMEM,
// scalar FFMA on position pairs, float4 constant-weight loads (IOK transposed),
// producer-push halo exchange via st.shared::cluster.

#define NTH 544
#define LBUF 2176
#define FRAME 128
#define TFULL 4096

typedef unsigned long long u64;

#define OC0   0
#define OCK   24      // [(i-1)*3+w][ci][co], co contiguous
#define OCB   1752    // [i][co]
#define OIOK  1832    // TRANSPOSED: [i][co][ci], ci contiguous
#define OIOB  2408    // [i][co]
#define OMIX  2480    // [i][co]
#define OMIXB 2560
#define NW    2561

__constant__ __align__(16) float Wc[NW];
__device__ float Wstage[NW];

__device__ __forceinline__ float4 F4(int idx) { return *(const float4*)&Wc[idx]; }

__device__ __forceinline__ uint32_t s2u(const void* p) {
    return (uint32_t)__cvta_generic_to_shared(p);
}
__device__ __forceinline__ uint32_t mapa_peer(uint32_t a, uint32_t peer) {
    uint32_t r;
    asm volatile("mapa.shared::cluster.u32 %0, %1, %2;" : "=r"(r) : "r"(a), "r"(peer));
    return r;
}
__device__ __forceinline__ void st_dsm64(uint32_t a, float x, float y) {
    u64 v = (u64)__float_as_uint(x) | ((u64)__float_as_uint(y) << 32);
    asm volatile("st.shared::cluster.b64 [%0], %1;" :: "r"(a), "l"(v) : "memory");
}
#define CS() do { asm volatile("barrier.cluster.arrive.aligned;" ::: "memory"); \
                  asm volatile("barrier.cluster.wait.aligned;" ::: "memory"); } while(0)

// M_i = 1086 + 2^(i+1) for S_i = 2*(2^(i+1)-1); derived: MSPLIT(S)=((S+LBUF)/2)&~1
#define MSPLIT(S) ((((S) + LBUF) / 2) & ~1)

__global__ void pack_weights(const float* __restrict__ c0,  const float* __restrict__ ck,
                             const float* __restrict__ cb,  const float* __restrict__ iok,
                             const float* __restrict__ iob, const float* __restrict__ mix,
                             const float* __restrict__ mixb) {
    int i = blockIdx.x * blockDim.x + threadIdx.x;
    if (i >= NW) return;
    float v;
    if      (i < OCK)   v = c0[i - OC0];
    else if (i < OCB)   v = ck[i - OCK];
    else if (i < OIOK)  v = cb[i - OCB];
    else if (i < OIOB) {                 // transpose io kernels: [i][co][ci] <- iok[i][ci][co]
        int j = i - OIOK, li = j >> 6, r = j & 63, co = r >> 3, ci = r & 7;
        v = iok[li * 64 + ci * 8 + co];
    }
    else if (i < OMIX)  v = iob[i - OIOB];
    else if (i < OMIXB) v = mix[i - OMIX];
    else                v = mixb[0];
    Wstage[i] = v;
}

extern __shared__ float smem[];

__global__ __launch_bounds__(NTH) __cluster_dims__(2, 1, 1)
void wavenet_kernel(const float* __restrict__ X, float* __restrict__ out)
{
    float* xb   = smem;              // LBUF
    float* hA   = smem + LBUF;       // 8*LBUF   h[c*LBUF + l]
    float* hB   = smem + 9 * LBUF;   // 8*LBUF
    float* oacc = smem + 17 * LBUF;  // FRAME

    const int tid = threadIdx.x;
    uint32_t rank;
    asm("mov.u32 %0, %%cluster_ctarank;" : "=r"(rank));
    const uint32_t peer = rank ^ 1u;
    const int b = blockIdx.x >> 1;
    const float* x = X + b * TFULL + (TFULL - LBUF);

    for (int l = tid; l < LBUF; l += NTH) xb[l] = x[l];
    if (rank && tid < FRAME) oacc[tid] = Wc[OMIXB];
    __syncthreads();

    // ---- layer 0 -> hA ----
    {
        const int S = 2, M = 1088, dn = 2;   // push window for layer-1 halo
        const int lo = rank ? M : S;
        const int hi = rank ? LBUF : M;
        const uint32_t pbase = mapa_peer(s2u(hA), peer);
        for (int l = lo + 2 * tid; l < hi; l += 2 * NTH) {
            float2 A = *(const float2*)&xb[l - 2];
            float2 B = *(const float2*)&xb[l];
            float wk0[8], wk1[8], wk2[8], cb[8];
            *(float4*)&wk0[0] = F4(OC0);      *(float4*)&wk0[4] = F4(OC0 + 4);
            *(float4*)&wk1[0] = F4(OC0 + 8);  *(float4*)&wk1[4] = F4(OC0 + 12);
            *(float4*)&wk2[0] = F4(OC0 + 16); *(float4*)&wk2[4] = F4(OC0 + 20);
            *(float4*)&cb[0]  = F4(OCB);      *(float4*)&cb[4]  = F4(OCB + 4);
            float acc0[8], acc1[8];
#pragma unroll
            for (int co = 0; co < 8; co++) {
                float a0 = fmaf(B.x, wk2[co], fmaf(A.y, wk1[co], fmaf(A.x, wk0[co], cb[co])));
                float a1 = fmaf(B.y, wk2[co], fmaf(B.x, wk1[co], fmaf(A.y, wk0[co], cb[co])));
                acc0[co] = fmaxf(a0, 0.0f);
                acc1[co] = fmaxf(a1, 0.0f);
            }
            if (l >= LBUF - FRAME) {
                float mw[8];
                *(float4*)&mw[0] = F4(OMIX); *(float4*)&mw[4] = F4(OMIX + 4);
                float m0 = 0.0f, m1 = 0.0f;
#pragma unroll
                for (int co = 0; co < 8; co++) { m0 = fmaf(acc0[co], mw[co], m0); m1 = fmaf(acc1[co], mw[co], m1); }
                oacc[l - (LBUF - FRAME)]     += m0;
                oacc[l - (LBUF - FRAME) + 1] += m1;
            }
            float iob[8];
            *(float4*)&iob[0] = F4(OIOB); *(float4*)&iob[4] = F4(OIOB + 4);
            const bool push = rank ? (l >= M && l < M + dn) : (l >= M - dn && l < M);
#pragma unroll
            for (int co = 0; co < 8; co++) {
                float tk[8];
                *(float4*)&tk[0] = F4(OIOK + co * 8); *(float4*)&tk[4] = F4(OIOK + co * 8 + 4);
                float a0 = iob[co] + B.x, a1 = iob[co] + B.y;
#pragma unroll
                for (int ci = 0; ci < 8; ci++) { a0 = fmaf(acc0[ci], tk[ci], a0); a1 = fmaf(acc1[ci], tk[ci], a1); }
                const int idx = co * LBUF + l;
                *(float2*)(hA + idx) = make_float2(a0, a1);
                if (push) st_dsm64(pbase + (uint32_t)idx * 4u, a0, a1);
            }
        }
    }
    CS();

    // ---- layers 1..8, ping-pong, producer-push halos ----
#pragma unroll
    for (int i = 1; i < 9; i++) {
        const int d  = 1 << i;
        const int S  = 2 * ((2 << i) - 1);
        const int M  = MSPLIT(S);            // = 1086 + 2^(i+1)
        const int dn = 2 << i;               // halo width for layer i+1
        float* cur = (i & 1) ? hA : hB;
        float* nxt = (i & 1) ? hB : hA;
        const uint32_t pbase = mapa_peer(s2u(nxt), peer);

        const int lo = rank ? M : S;
        const int hi = rank ? LBUF : M;
        for (int l = lo + 2 * tid; l < hi; l += 2 * NTH) {
            float acc0[8], acc1[8], hl0[8], hl1[8];
            {
                float cb[8];
                *(float4*)&cb[0] = F4(OCB + i * 8); *(float4*)&cb[4] = F4(OCB + i * 8 + 4);
#pragma unroll
                for (int co = 0; co < 8; co++) { acc0[co] = cb[co]; acc1[co] = cb[co]; }
            }
#pragma unroll
            for (int w = 0; w < 3; w++) {
                const int off = (2 - w) * d;
#pragma unroll
                for (int ci = 0; ci < 8; ci++) {
                    float2 v = *(const float2*)(cur + ci * LBUF + (l - off));
                    if (w == 2) { hl0[ci] = v.x; hl1[ci] = v.y; }
                    const int wb = OCK + (((i - 1) * 3 + w) * 8 + ci) * 8;
                    float wk[8];
                    *(float4*)&wk[0] = F4(wb); *(float4*)&wk[4] = F4(wb + 4);
#pragma unroll
                    for (int co = 0; co < 8; co++) {
                        acc0[co] = fmaf(v.x, wk[co], acc0[co]);
                        acc1[co] = fmaf(v.y, wk[co], acc1[co]);
                    }
                }
            }
#pragma unroll
            for (int co = 0; co < 8; co++) {
                acc0[co] = fmaxf(acc0[co], 0.0f);
                acc1[co] = fmaxf(acc1[co], 0.0f);
            }
            if (l >= LBUF - FRAME) {
                float mw[8];
                *(float4*)&mw[0] = F4(OMIX + i * 8); *(float4*)&mw[4] = F4(OMIX + i * 8 + 4);
                float m0 = 0.0f, m1 = 0.0f;
#pragma unroll
                for (int co = 0; co < 8; co++) { m0 = fmaf(acc0[co], mw[co], m0); m1 = fmaf(acc1[co], mw[co], m1); }
                oacc[l - (LBUF - FRAME)]     += m0;
                oacc[l - (LBUF - FRAME) + 1] += m1;
            }
            float iob[8];
            *(float4*)&iob[0] = F4(OIOB + i * 8); *(float4*)&iob[4] = F4(OIOB + i * 8 + 4);
            bool push;
            if (i == 8)   // layer 9 runs only on rank1; rank0 pushes the two strips it owns
                push = rank ? false
                            : ((l >= 1024 && l < 1152) || (l >= 1536 && l < MSPLIT(1022)));
            else
                push = rank ? (l >= M && l < M + dn) : (l >= M - dn && l < M);
#pragma unroll
            for (int co = 0; co < 8; co++) {
                float tk[8];
                *(float4*)&tk[0] = F4(OIOK + i * 64 + co * 8);
                *(float4*)&tk[4] = F4(OIOK + i * 64 + co * 8 + 4);
                float a0 = iob[co] + hl0[co], a1 = iob[co] + hl1[co];
#pragma unroll
                for (int ci = 0; ci < 8; ci++) { a0 = fmaf(acc0[ci], tk[ci], a0); a1 = fmaf(acc1[ci], tk[ci], a1); }
                const int idx = co * LBUF + l;
                *(float2*)(nxt + idx) = make_float2(a0, a1);
                if (push) st_dsm64(pbase + (uint32_t)idx * 4u, a0, a1);
            }
        }
        CS();
    }

    // ---- layer 9: rank1 only, reads entirely from its own hA ----
    if (rank) {
        const int i = 9, d = 512;
        for (int l = (LBUF - FRAME) + 2 * tid; l < LBUF; l += 2 * NTH) {
            float acc0[8], acc1[8];
            {
                float cb[8];
                *(float4*)&cb[0] = F4(OCB + i * 8); *(float4*)&cb[4] = F4(OCB + i * 8 + 4);
#pragma unroll
                for (int co = 0; co < 8; co++) { acc0[co] = cb[co]; acc1[co] = cb[co]; }
            }
#pragma unroll
            for (int w = 0; w < 3; w++) {
                const int off = (2 - w) * d;
#pragma unroll
                for (int ci = 0; ci < 8; ci++) {
                    float2 v = *(const float2*)(hA + ci * LBUF + (l - off));
                    const int wb = OCK + (((i - 1) * 3 + w) * 8 + ci) * 8;
                    float wk[8];
                    *(float4*)&wk[0] = F4(wb); *(float4*)&wk[4] = F4(wb + 4);
#pragma unroll
                    for (int co = 0; co < 8; co++) {
                        acc0[co] = fmaf(v.x, wk[co], acc0[co]);
                        acc1[co] = fmaf(v.y, wk[co], acc1[co]);
                    }
                }
            }
            float mw[8];
            *(float4*)&mw[0] = F4(OMIX + i * 8); *(float4*)&mw[4] = F4(OMIX + i * 8 + 4);
            float m0 = 0.0f, m1 = 0.0f;
#pragma unroll
            for (int co = 0; co < 8; co++) {
                m0 = fmaf(fmaxf(acc0[co], 0.0f), mw[co], m0);
                m1 = fmaf(fmaxf(acc1[co], 0.0f), mw[co], m1);
            }
            oacc[l - (LBUF - FRAME)]     += m0;
            oacc[l - (LBUF - FRAME) + 1] += m1;
        }
        __syncthreads();
        for (int j = tid; j < FRAME; j += NTH) out[b * FRAME + j] = oacc[j];
    }
}

static const int SMEM_BYTES = (17 * LBUF + FRAME) * (int)sizeof(float);

extern "C" void kernel_launch(void* const* d_in, const int* in_sizes, int n_in,
                              void* d_out, int out_size) {
    (void)in_sizes; (void)n_in; (void)out_size;
    cudaFuncSetAttribute(wavenet_kernel, cudaFuncAttributeMaxDynamicSharedMemorySize, SMEM_BYTES);

    pack_weights<<<(NW + 511) / 512, 512>>>(
        (const float*)d_in[1], (const float*)d_in[2], (const float*)d_in[3],
        (const float*)d_in[4], (const float*)d_in[5], (const float*)d_in[6],
        (const float*)d_in[7]);

    void* wp = nullptr;
    cudaGetSymbolAddress(&wp, Wstage);
    cudaMemcpyToSymbolAsync(Wc, wp, NW * sizeof(float), 0, cudaMemcpyDeviceToDevice, 0);

    wavenet_kernel<<<128, NTH, SMEM_BYTES>>>((const float*)d_in[0], (float*)d_out);
}